// round 2
// baseline (speedup 1.0000x reference)
#include <cuda_runtime.h>
#include <cuda_bf16.h>
#include <cstdint>

// ---------------- problem constants ----------------
#define NIMG   8192
#define C1     20
#define C2     50
#define P1PIX  196          // 14*14 pooled pixels after stage 1
#define LIN_IN 1250
#define LIN_P  1280         // padded to multiple of 16
#define LIN_OUT 500
#define NCLS   10

// ---------------- device scratch (static, allowed) ----------------
__device__ float        g_part[NIMG * C1];          // per-image channel sums
__device__ float        g_mean[C1];                 // BN channel means
__device__ unsigned int g_b1p[NIMG * P1PIX];        // stage-1 bits, 20 bits/pixel
__device__ int2         g_w2p[C2 * 25];             // conv2 (pos,neg) masks per (oc,tap)
__device__ signed char  g_swl[LIN_OUT * LIN_P];     // sign(lin_w), zero-padded
__device__ float        g_alphal[LIN_OUT];          // mean |lin_w| per row
__device__ signed char  g_s2[NIMG * LIN_P];         // stage-2 signs, padded
__device__ float        g_a3[NIMG * LIN_OUT];       // clipped linear output

// ================= weight preprocessing =================
__global__ void kw_pack(const float* __restrict__ w2, const float* __restrict__ wl) {
    int gid = blockIdx.x * blockDim.x + threadIdx.x;
    int stride = gridDim.x * blockDim.x;
    // conv2 sign masks: w2 layout [oc][ic][ky][kx]
    for (int i = gid; i < C2 * 25; i += stride) {
        int oc = i / 25, p = i % 25;
        unsigned wp = 0, wn = 0;
        for (int ic = 0; ic < C1; ic++) {
            float v = w2[(oc * C1 + ic) * 25 + p];
            if (v > 0.f) wp |= (1u << ic);
            else if (v < 0.f) wn |= (1u << ic);
        }
        g_w2p[i] = make_int2((int)wp, (int)wn);
    }
    // linear sign weights (padded)
    for (int i = gid; i < LIN_OUT * LIN_P; i += stride) {
        int oc = i / LIN_P, k = i % LIN_P;
        signed char s = 0;
        if (k < LIN_IN) {
            float v = wl[oc * LIN_IN + k];
            s = (signed char)((v > 0.f) - (v < 0.f));
        }
        g_swl[i] = s;
    }
}

__global__ void kw_alpha(const float* __restrict__ wl) {
    int oc = blockIdx.x * blockDim.x + threadIdx.x;
    if (oc >= LIN_OUT) return;
    float s = 0.f;
    for (int k = 0; k < LIN_IN; k++) s += fabsf(wl[oc * LIN_IN + k]);
    g_alphal[oc] = s * (1.f / (float)LIN_IN);
}

// ================= k1: per-image conv1 channel sums via window sums =================
__global__ void k1_stats(const float* __restrict__ x, const float* __restrict__ w1) {
    int img = blockIdx.x, t = threadIdx.x;         // 256 threads
    __shared__ float sR[32 * 5];                   // R[row][kx]
    __shared__ float sS[25];
    __shared__ float sw[C1 * 25];
    for (int i = t; i < C1 * 25; i += 256) sw[i] = w1[i];
    int warp = t >> 5, lane = t & 31;
    for (int r = warp; r < 32; r += 8) {
        float v = x[img * 1024 + r * 32 + lane];
        float p = v;
#pragma unroll
        for (int off = 1; off < 32; off <<= 1) {
            float o = __shfl_up_sync(0xffffffffu, p, off);
            if (lane >= off) p += o;
        }
        float lo = __shfl_up_sync(0xffffffffu, p, 1);
        if (lane == 0) lo = 0.f;
        float hi = __shfl_sync(0xffffffffu, p, (lane + 27) & 31);
        if (lane < 5) sR[r * 5 + lane] = hi - lo;   // sum of x[r][kx..kx+27]
    }
    __syncthreads();
    if (t < 25) {
        int ky = t / 5, kx = t % 5;
        float s = 0.f;
        for (int r = ky; r < ky + 28; r++) s += sR[r * 5 + kx];
        sS[t] = s;
    }
    __syncthreads();
    if (t < C1) {
        float a = 0.f;
#pragma unroll
        for (int p = 0; p < 25; p++) a += sw[t * 25 + p] * sS[p];
        g_part[img * C1 + t] = a;
    }
}

// ================= k2: deterministic channel-mean reduction =================
__global__ void k2_mean() {
    int c = blockIdx.x, t = threadIdx.x;           // 20 blocks x 256
    __shared__ float red[256];
    float s = 0.f;
    for (int i = t; i < NIMG; i += 256) s += g_part[i * C1 + c];
    red[t] = s;
    __syncthreads();
    for (int o = 128; o > 0; o >>= 1) {
        if (t < o) red[t] += red[t + o];
        __syncthreads();
    }
    if (t == 0) g_mean[c] = red[0] * (1.0f / (8192.f * 784.f));
}

// ================= k3: conv1 + BN-threshold + maxpool + sign (bitpack) =================
__global__ void __launch_bounds__(256) k3_conv1(const float* __restrict__ x,
                                                const float* __restrict__ w1) {
    __shared__ float sx[1024];
    __shared__ float sw[C1 * 25];
    __shared__ float sm[C1];
    int img = blockIdx.x, t = threadIdx.x;
    for (int i = t; i < 1024; i += 256) sx[i] = x[img * 1024 + i];
    for (int i = t; i < C1 * 25; i += 256) sw[i] = w1[i];
    if (t < C1) sm[t] = g_mean[t];
    __syncthreads();
    if (t < P1PIX) {
        int py = t / 14, px = t % 14;
        float win[6][6];
#pragma unroll
        for (int r = 0; r < 6; r++)
#pragma unroll
            for (int cc = 0; cc < 6; cc++)
                win[r][cc] = sx[(py * 2 + r) * 32 + px * 2 + cc];
        unsigned int bits = 0;
        for (int c = 0; c < C1; c++) {
            float wv[25];
#pragma unroll
            for (int p = 0; p < 25; p++) wv[p] = sw[c * 25 + p];
            float m = -1e30f;
#pragma unroll
            for (int dy = 0; dy < 2; dy++)
#pragma unroll
                for (int dx = 0; dx < 2; dx++) {
                    float acc = 0.f;
#pragma unroll
                    for (int ky = 0; ky < 5; ky++)
#pragma unroll
                        for (int kx = 0; kx < 5; kx++)
                            acc += win[dy + ky][dx + kx] * wv[ky * 5 + kx];
                    m = fmaxf(m, acc);
                }
            if (m > sm[c]) bits |= (1u << c);
        }
        g_b1p[img * P1PIX + t] = bits;
    }
}

// ================= k4: XNOR conv2 + pool + sign (popcount) =================
__global__ void __launch_bounds__(256) k4_conv2() {
    __shared__ unsigned int sb[P1PIX];
    __shared__ int2 sw2[C2 * 25];
    int img = blockIdx.x, t = threadIdx.x;
    for (int i = t; i < P1PIX; i += 256) sb[i] = g_b1p[img * P1PIX + i];
    for (int i = t; i < C2 * 25; i += 256) sw2[i] = g_w2p[i];
    __syncthreads();
    for (int idx = t; idx < LIN_P; idx += 256) {
        if (idx >= LIN_IN) { g_s2[img * LIN_P + idx] = 0; continue; }
        int oc = idx / 25, pp = idx % 25;
        int py = pp / 5, px = pp % 5;
        unsigned int win[6][6];
#pragma unroll
        for (int r = 0; r < 6; r++)
#pragma unroll
            for (int cc = 0; cc < 6; cc++)
                win[r][cc] = sb[(py * 2 + r) * 14 + px * 2 + cc];
        int a0 = 0, a1 = 0, a2 = 0, a3 = 0;
#pragma unroll
        for (int ky = 0; ky < 5; ky++)
#pragma unroll
            for (int kx = 0; kx < 5; kx++) {
                int2 w = sw2[oc * 25 + ky * 5 + kx];
                unsigned wp = (unsigned)w.x, wn = (unsigned)w.y;
                a0 += __popc(win[ky    ][kx    ] & wp) - __popc(win[ky    ][kx    ] & wn);
                a1 += __popc(win[ky    ][kx + 1] & wp) - __popc(win[ky    ][kx + 1] & wn);
                a2 += __popc(win[ky + 1][kx    ] & wp) - __popc(win[ky + 1][kx    ] & wn);
                a3 += __popc(win[ky + 1][kx + 1] & wp) - __popc(win[ky + 1][kx + 1] & wn);
            }
        int best = max(max(a0, a1), max(a2, a3));
        g_s2[img * LIN_P + idx] = (signed char)((best > 0) - (best < 0));
    }
}

// ================= k5: binary linear (dp4a) + alpha + clip =================
__global__ void __launch_bounds__(256) k5_linear() {
    __shared__ int4 ss[16 * (LIN_P / 16)];   // 16 samples x 80 int4 = 20 KB
    int blk = blockIdx.x, t = threadIdx.x;   // 512 blocks
    int n0 = blk * 16;
    const int4* src = (const int4*)(g_s2 + (size_t)n0 * LIN_P);
    for (int i = t; i < 16 * 80; i += 256) ss[i] = src[i];
    __syncthreads();
    for (int oc = t; oc < LIN_OUT; oc += 256) {
        float al = g_alphal[oc];
        const int4* wr = (const int4*)(g_swl + (size_t)oc * LIN_P);
        int acc[16];
#pragma unroll
        for (int n = 0; n < 16; n++) acc[n] = 0;
        for (int c = 0; c < 80; c++) {
            int4 w = wr[c];
#pragma unroll
            for (int n = 0; n < 16; n++) {
                int4 s = ss[n * 80 + c];    // broadcast across warp (same addr)
                int a = acc[n];
                a = __dp4a(s.x, w.x, a);
                a = __dp4a(s.y, w.y, a);
                a = __dp4a(s.z, w.z, a);
                a = __dp4a(s.w, w.w, a);
                acc[n] = a;
            }
        }
#pragma unroll
        for (int n = 0; n < 16; n++) {
            float v = (float)acc[n] * al;
            v = fminf(1.f, fmaxf(-1.f, v));
            g_a3[(size_t)(n0 + n) * LIN_OUT + oc] = v;
        }
    }
}

// ================= k6: final fc =================
__global__ void k6_fc(const float* __restrict__ fcw, const float* __restrict__ fcb,
                      float* __restrict__ out) {
    int gid = blockIdx.x * blockDim.x + threadIdx.x;
    if (gid >= NIMG * NCLS) return;
    int n = gid / NCLS, cls = gid % NCLS;
    const float* a = g_a3 + (size_t)n * LIN_OUT;
    const float* w = fcw + cls * LIN_OUT;
    float acc = 0.f;
#pragma unroll 4
    for (int k = 0; k < LIN_OUT; k++) acc += a[k] * w[k];
    out[gid] = acc + fcb[cls];
}

// ================= launch =================
extern "C" void kernel_launch(void* const* d_in, const int* in_sizes, int n_in,
                              void* d_out, int out_size) {
    const float* x   = (const float*)d_in[0];
    const float* w1  = (const float*)d_in[1];
    const float* w2  = (const float*)d_in[2];
    const float* wl  = (const float*)d_in[3];
    const float* fcw = (const float*)d_in[4];
    const float* fcb = (const float*)d_in[5];
    float* out = (float*)d_out;

    kw_pack  <<<256, 256>>>(w2, wl);
    kw_alpha <<<2, 256>>>(wl);
    k1_stats <<<NIMG, 256>>>(x, w1);
    k2_mean  <<<C1, 256>>>();
    k3_conv1 <<<NIMG, 256>>>(x, w1);
    k4_conv2 <<<NIMG, 256>>>();
    k5_linear<<<NIMG / 16, 256>>>();
    k6_fc    <<<(NIMG * NCLS + 255) / 256, 256>>>(fcw, fcb, out);
}

// round 3
// speedup vs baseline: 1.5440x; 1.5440x over previous
#include <cuda_runtime.h>
#include <cuda_bf16.h>
#include <cstdint>

// ---------------- problem constants ----------------
#define NIMG   8192
#define C1     20
#define C2     50
#define P1PIX  196          // 14*14 pooled pixels after stage 1
#define LIN_IN 1250
#define NWRD   40           // ceil(1250/32)
#define LIN_OUT 500
#define NCLS   10
#define IMGB   16           // images per k5 block

// ---------------- device scratch ----------------
__device__ float        g_part[NIMG * C1];
__device__ float        g_mean[C1];
__device__ unsigned int g_b1p[NIMG * P1PIX];        // stage-1 bits, 20/pixel
__device__ unsigned int g_w2p[C2 * 25];             // conv2 positive-sign masks
__device__ unsigned int g_wpl[LIN_OUT * NWRD];      // linear positive-sign bitmask
__device__ float        g_alphal[LIN_OUT];
__device__ uint2        g_s2p[NIMG * NWRD];         // stage-2 (sp, sn) bit words

// ---------------- f32x2 helpers ----------------
__device__ __forceinline__ unsigned long long pack2(float lo, float hi) {
    unsigned long long r;
    asm("mov.b64 %0, {%1, %2};" : "=l"(r) : "f"(lo), "f"(hi));
    return r;
}
__device__ __forceinline__ void unpack2(unsigned long long v, float& lo, float& hi) {
    asm("mov.b64 {%0, %1}, %2;" : "=f"(lo), "=f"(hi) : "l"(v));
}
__device__ __forceinline__ unsigned long long fma2(unsigned long long a,
                                                   unsigned long long b,
                                                   unsigned long long c) {
    unsigned long long d;
    asm("fma.rn.f32x2 %0, %1, %2, %3;" : "=l"(d) : "l"(a), "l"(b), "l"(c));
    return d;
}

// ================= kw: weight preprocessing (all-in-one) =================
__global__ void kw_pack(const float* __restrict__ w2, const float* __restrict__ wl) {
    int gid = blockIdx.x * blockDim.x + threadIdx.x;
    int stride = gridDim.x * blockDim.x;
    // conv2 positive masks (weights are never exactly 0)
    for (int i = gid; i < C2 * 25; i += stride) {
        int oc = i / 25, p = i % 25;
        unsigned wp = 0;
        for (int ic = 0; ic < C1; ic++)
            if (w2[(oc * C1 + ic) * 25 + p] > 0.f) wp |= (1u << ic);
        g_w2p[i] = wp;
    }
    // linear sign bitmask, padded words zero-irrelevant
    for (int i = gid; i < LIN_OUT * NWRD; i += stride) {
        int oc = i / NWRD, w = i % NWRD;
        unsigned bits = 0;
        for (int j = 0; j < 32; j++) {
            int k = w * 32 + j;
            if (k < LIN_IN && wl[oc * LIN_IN + k] > 0.f) bits |= (1u << j);
        }
        g_wpl[i] = bits;
    }
    // alpha
    for (int oc = gid; oc < LIN_OUT; oc += stride) {
        float s = 0.f;
        for (int k = 0; k < LIN_IN; k++) s += fabsf(wl[oc * LIN_IN + k]);
        g_alphal[oc] = s * (1.f / (float)LIN_IN);
    }
}

// ================= k1: per-image conv1 channel sums via window sums =================
__global__ void k1_stats(const float* __restrict__ x, const float* __restrict__ w1) {
    int img = blockIdx.x, t = threadIdx.x;         // 256 threads
    __shared__ float sR[32 * 5];
    __shared__ float sS[25];
    __shared__ float sw[C1 * 25];
    for (int i = t; i < C1 * 25; i += 256) sw[i] = w1[i];
    int warp = t >> 5, lane = t & 31;
    for (int r = warp; r < 32; r += 8) {
        float v = x[img * 1024 + r * 32 + lane];
        float p = v;
#pragma unroll
        for (int off = 1; off < 32; off <<= 1) {
            float o = __shfl_up_sync(0xffffffffu, p, off);
            if (lane >= off) p += o;
        }
        float lo = __shfl_up_sync(0xffffffffu, p, 1);
        if (lane == 0) lo = 0.f;
        float hi = __shfl_sync(0xffffffffu, p, (lane + 27) & 31);
        if (lane < 5) sR[r * 5 + lane] = hi - lo;
    }
    __syncthreads();
    if (t < 25) {
        int ky = t / 5, kx = t % 5;
        float s = 0.f;
        for (int r = ky; r < ky + 28; r++) s += sR[r * 5 + kx];
        sS[t] = s;
    }
    __syncthreads();
    if (t < C1) {
        float a = 0.f;
#pragma unroll
        for (int p = 0; p < 25; p++) a += sw[t * 25 + p] * sS[p];
        g_part[img * C1 + t] = a;
    }
}

// ================= k2: deterministic channel-mean reduction =================
__global__ void k2_mean() {
    int c = blockIdx.x, t = threadIdx.x;
    __shared__ float red[256];
    float s = 0.f;
    for (int i = t; i < NIMG; i += 256) s += g_part[i * C1 + c];
    red[t] = s;
    __syncthreads();
    for (int o = 128; o > 0; o >>= 1) {
        if (t < o) red[t] += red[t + o];
        __syncthreads();
    }
    if (t == 0) g_mean[c] = red[0] * (1.0f / (8192.f * 784.f));
}

// ================= k3: conv1 + threshold + pool + sign, FFMA2 =================
__global__ void __launch_bounds__(224) k3_conv1(const float* __restrict__ x,
                                                const float* __restrict__ w1) {
    __shared__ float sx[1024];
    __shared__ unsigned long long swd[C1 * 25];   // weight duplicated in both halves
    __shared__ float sm[C1];
    int img = blockIdx.x, t = threadIdx.x;
    for (int i = t; i < 1024; i += 224) sx[i] = x[img * 1024 + i];
    for (int i = t; i < C1 * 25; i += 224) {
        float v = w1[i];
        swd[i] = pack2(v, v);
    }
    if (t < C1) sm[t] = g_mean[t];
    __syncthreads();
    if (t < P1PIX) {
        int py = t / 14, px = t % 14;
        // packed pairs: P[r][k] = (win[r][k], win[r][k+1])  — positions dx=0 / dx=1
        unsigned long long P[6][5];
#pragma unroll
        for (int r = 0; r < 6; r++) {
            float c0 = sx[(py * 2 + r) * 32 + px * 2 + 0];
            float c1 = sx[(py * 2 + r) * 32 + px * 2 + 1];
            float c2 = sx[(py * 2 + r) * 32 + px * 2 + 2];
            float c3 = sx[(py * 2 + r) * 32 + px * 2 + 3];
            float c4 = sx[(py * 2 + r) * 32 + px * 2 + 4];
            float c5 = sx[(py * 2 + r) * 32 + px * 2 + 5];
            P[r][0] = pack2(c0, c1);
            P[r][1] = pack2(c1, c2);
            P[r][2] = pack2(c2, c3);
            P[r][3] = pack2(c3, c4);
            P[r][4] = pack2(c4, c5);
        }
        unsigned int bits = 0;
#pragma unroll 1
        for (int c = 0; c < C1; c++) {
            unsigned long long a0 = 0ull, a1 = 0ull;   // dy=0 / dy=1 (both dx in halves)
#pragma unroll
            for (int p = 0; p < 25; p++) {
                unsigned long long w = swd[c * 25 + p];
                a0 = fma2(P[p / 5][p % 5], w, a0);
                a1 = fma2(P[p / 5 + 1][p % 5], w, a1);
            }
            float f00, f01, f10, f11;
            unpack2(a0, f00, f01);
            unpack2(a1, f10, f11);
            float m = fmaxf(fmaxf(f00, f01), fmaxf(f10, f11));
            if (m > sm[c]) bits |= (1u << c);
        }
        g_b1p[img * P1PIX + t] = bits;
    }
}

// ================= k4: XNOR conv2 + pool + sign -> ballot bitpack =================
__global__ void __launch_bounds__(256) k4_conv2() {
    __shared__ unsigned int sb[P1PIX];
    __shared__ unsigned int sw2[C2 * 25];
    __shared__ int spc[P1PIX];
    __shared__ int sS[100];
    int img = blockIdx.x, t = threadIdx.x;
    for (int i = t; i < P1PIX; i += 256) sb[i] = g_b1p[img * P1PIX + i];
    for (int i = t; i < C2 * 25; i += 256) sw2[i] = g_w2p[i];
    __syncthreads();
    if (t < P1PIX) spc[t] = __popc(sb[t]);
    __syncthreads();
    if (t < 100) {
        int py = t / 10, px = t % 10;
        int s = 0;
#pragma unroll
        for (int ky = 0; ky < 5; ky++)
#pragma unroll
            for (int kx = 0; kx < 5; kx++)
                s += spc[(py + ky) * 14 + px + kx];
        sS[t] = s;
    }
    __syncthreads();
    int lane = t & 31;
    for (int idx = t; idx < 1280; idx += 256) {
        int best = 0;
        if (idx < LIN_IN) {
            int oc = idx / 25, pp = idx % 25;
            int py = pp / 5, px = pp % 5;
            unsigned int win[6][6];
#pragma unroll
            for (int r = 0; r < 6; r++)
#pragma unroll
                for (int cc = 0; cc < 6; cc++)
                    win[r][cc] = sb[(py * 2 + r) * 14 + px * 2 + cc];
            int A0 = 0, A1 = 0, A2 = 0, A3 = 0;
#pragma unroll
            for (int ky = 0; ky < 5; ky++)
#pragma unroll
                for (int kx = 0; kx < 5; kx++) {
                    unsigned wp = sw2[oc * 25 + ky * 5 + kx];
                    A0 += __popc(win[ky][kx] & wp);
                    A1 += __popc(win[ky][kx + 1] & wp);
                    A2 += __popc(win[ky + 1][kx] & wp);
                    A3 += __popc(win[ky + 1][kx + 1] & wp);
                }
            int a0 = 2 * A0 - sS[(2 * py) * 10 + 2 * px];
            int a1 = 2 * A1 - sS[(2 * py) * 10 + 2 * px + 1];
            int a2 = 2 * A2 - sS[(2 * py + 1) * 10 + 2 * px];
            int a3 = 2 * A3 - sS[(2 * py + 1) * 10 + 2 * px + 1];
            best = max(max(a0, a1), max(a2, a3));
        }
        unsigned bp = __ballot_sync(0xffffffffu, best > 0);
        unsigned bn = __ballot_sync(0xffffffffu, best < 0);
        if (lane == 0) g_s2p[img * NWRD + (idx >> 5)] = make_uint2(bp, bn);
    }
}

// ================= k5: popcount ternary linear + alpha + clip + fused fc =================
__global__ void __launch_bounds__(256) k5_linear(const float* __restrict__ fcw,
                                                 const float* __restrict__ fcb,
                                                 float* __restrict__ out) {
    __shared__ uint2 s2[IMGB * NWRD];     // (sp, sn) words
    __shared__ int   sD[IMGB];            // PSP - PSN per image
    __shared__ float sa[IMGB * LIN_OUT];  // clipped activations, 32 KB
    int blk = blockIdx.x, t = threadIdx.x;
    int n0 = blk * IMGB;
    for (int i = t; i < IMGB * NWRD; i += 256) s2[i] = g_s2p[n0 * NWRD + i];
    __syncthreads();
    if (t < IMGB) {
        int d = 0;
#pragma unroll
        for (int w = 0; w < NWRD; w++) {
            uint2 s = s2[t * NWRD + w];
            d += __popc(s.x) - __popc(s.y);
        }
        sD[t] = d;
    }
    __syncthreads();
    for (int oc = t; oc < LIN_OUT; oc += 256) {
        float al = g_alphal[oc];
        const unsigned int* wr = g_wpl + oc * NWRD;
        int acc[IMGB];
#pragma unroll
        for (int n = 0; n < IMGB; n++) acc[n] = 0;
#pragma unroll 4
        for (int w = 0; w < NWRD; w++) {
            unsigned wv = wr[w];
#pragma unroll
            for (int n = 0; n < IMGB; n++) {
                uint2 s = s2[n * NWRD + w];
                acc[n] += __popc(s.x & wv) - __popc(s.y & wv);
            }
        }
#pragma unroll
        for (int n = 0; n < IMGB; n++) {
            float v = (float)(2 * acc[n] - sD[n]) * al;
            v = fminf(1.f, fmaxf(-1.f, v));
            sa[n * LIN_OUT + oc] = v;
        }
    }
    __syncthreads();
    // fused fc: 16 images x 10 classes
    for (int i = t; i < IMGB * NCLS; i += 256) {
        int n = i / NCLS, cls = i % NCLS;
        const float* a = sa + n * LIN_OUT;
        const float* w = fcw + cls * LIN_OUT;
        float acc = 0.f;
#pragma unroll 4
        for (int k = 0; k < LIN_OUT; k++) acc += a[k] * w[k];
        out[(n0 + n) * NCLS + cls] = acc + fcb[cls];
    }
}

// ================= launch =================
extern "C" void kernel_launch(void* const* d_in, const int* in_sizes, int n_in,
                              void* d_out, int out_size) {
    const float* x   = (const float*)d_in[0];
    const float* w1  = (const float*)d_in[1];
    const float* w2  = (const float*)d_in[2];
    const float* wl  = (const float*)d_in[3];
    const float* fcw = (const float*)d_in[4];
    const float* fcb = (const float*)d_in[5];
    float* out = (float*)d_out;

    kw_pack  <<<256, 256>>>(w2, wl);
    k1_stats <<<NIMG, 256>>>(x, w1);
    k2_mean  <<<C1, 256>>>();
    k3_conv1 <<<NIMG, 224>>>(x, w1);
    k4_conv2 <<<NIMG, 256>>>();
    k5_linear<<<NIMG / IMGB, 256>>>(fcw, fcb, out);
}

// round 4
// speedup vs baseline: 1.7484x; 1.1324x over previous
#include <cuda_runtime.h>
#include <cuda_bf16.h>
#include <cstdint>

// ---------------- problem constants ----------------
#define NIMG   8192
#define C1     20
#define C2     50
#define P1PIX  196          // 14*14 pooled pixels after stage 1
#define LIN_IN 1250
#define NWRD   40           // ceil(1250/32)
#define LIN_OUT 500
#define NCLS   10
#define IMGB   16           // images per k5 block

// ---------------- device scratch ----------------
__device__ float        g_part[NIMG * C1];
__device__ float        g_mean[C1];
__device__ unsigned int g_b1p[NIMG * P1PIX];        // stage-1 bits, 20/pixel
__device__ unsigned int g_w2p[C2 * 25];             // conv2 positive-sign masks
__device__ unsigned int g_wpl[LIN_OUT * NWRD];      // linear positive-sign bitmask
__device__ float        g_alphal[LIN_OUT];
__device__ uint2        g_s2p[NIMG * NWRD];         // stage-2 (sp, sn) bit words

// ---------------- f32x2 helpers ----------------
__device__ __forceinline__ unsigned long long pack2(float lo, float hi) {
    unsigned long long r;
    asm("mov.b64 %0, {%1, %2};" : "=l"(r) : "f"(lo), "f"(hi));
    return r;
}
__device__ __forceinline__ void unpack2(unsigned long long v, float& lo, float& hi) {
    asm("mov.b64 {%0, %1}, %2;" : "=f"(lo), "=f"(hi) : "l"(v));
}
__device__ __forceinline__ unsigned long long fma2(unsigned long long a,
                                                   unsigned long long b,
                                                   unsigned long long c) {
    unsigned long long d;
    asm("fma.rn.f32x2 %0, %1, %2, %3;" : "=l"(d) : "l"(a), "l"(b), "l"(c));
    return d;
}

// ================= kw: weight preprocessing (all-in-one) =================
__global__ void kw_pack(const float* __restrict__ w2, const float* __restrict__ wl) {
    int gid = blockIdx.x * blockDim.x + threadIdx.x;
    int stride = gridDim.x * blockDim.x;
    // conv2 positive masks (weights are never exactly 0)
    for (int i = gid; i < C2 * 25; i += stride) {
        int oc = i / 25, p = i % 25;
        unsigned wp = 0;
        for (int ic = 0; ic < C1; ic++)
            if (w2[(oc * C1 + ic) * 25 + p] > 0.f) wp |= (1u << ic);
        g_w2p[i] = wp;
    }
    // linear sign bitmask
    for (int i = gid; i < LIN_OUT * NWRD; i += stride) {
        int oc = i / NWRD, w = i % NWRD;
        unsigned bits = 0;
        for (int j = 0; j < 32; j++) {
            int k = w * 32 + j;
            if (k < LIN_IN && wl[oc * LIN_IN + k] > 0.f) bits |= (1u << j);
        }
        g_wpl[i] = bits;
    }
    // alpha: one warp per output row (order change is continuous-path-safe)
    for (int i = gid; i < LIN_OUT * 32; i += stride) {
        int oc = i >> 5, lane = i & 31;
        float s = 0.f;
        for (int k = lane; k < LIN_IN; k += 32) s += fabsf(wl[oc * LIN_IN + k]);
#pragma unroll
        for (int off = 16; off > 0; off >>= 1)
            s += __shfl_down_sync(0xffffffffu, s, off);
        if (lane == 0) g_alphal[oc] = s * (1.f / (float)LIN_IN);
    }
}

// ================= k1: per-image conv1 channel sums via window sums =================
__global__ void k1_stats(const float* __restrict__ x, const float* __restrict__ w1) {
    int img = blockIdx.x, t = threadIdx.x;         // 256 threads
    __shared__ float sR[32 * 5];
    __shared__ float sS[25];
    __shared__ float sw[C1 * 25];
    for (int i = t; i < C1 * 25; i += 256) sw[i] = w1[i];
    int warp = t >> 5, lane = t & 31;
    for (int r = warp; r < 32; r += 8) {
        float v = x[img * 1024 + r * 32 + lane];
        float p = v;
#pragma unroll
        for (int off = 1; off < 32; off <<= 1) {
            float o = __shfl_up_sync(0xffffffffu, p, off);
            if (lane >= off) p += o;
        }
        float lo = __shfl_up_sync(0xffffffffu, p, 1);
        if (lane == 0) lo = 0.f;
        float hi = __shfl_sync(0xffffffffu, p, (lane + 27) & 31);
        if (lane < 5) sR[r * 5 + lane] = hi - lo;
    }
    __syncthreads();
    if (t < 25) {
        int ky = t / 5, kx = t % 5;
        float s = 0.f;
        for (int r = ky; r < ky + 28; r++) s += sR[r * 5 + kx];
        sS[t] = s;
    }
    __syncthreads();
    if (t < C1) {
        float a = 0.f;
#pragma unroll
        for (int p = 0; p < 25; p++) a += sw[t * 25 + p] * sS[p];
        g_part[img * C1 + t] = a;
    }
}

// ================= k2: deterministic channel-mean reduction =================
__global__ void k2_mean() {
    int c = blockIdx.x, t = threadIdx.x;
    __shared__ float red[256];
    float s = 0.f;
    for (int i = t; i < NIMG; i += 256) s += g_part[i * C1 + c];
    red[t] = s;
    __syncthreads();
    for (int o = 128; o > 0; o >>= 1) {
        if (t < o) red[t] += red[t + o];
        __syncthreads();
    }
    if (t == 0) g_mean[c] = red[0] * (1.0f / (8192.f * 784.f));
}

// ================= k3: conv1 + threshold + pool + sign, FFMA2 + LDS.128 =================
__global__ void __launch_bounds__(224) k3_conv1(const float* __restrict__ x,
                                                const float* __restrict__ w1) {
    __shared__ float sx[1024];
    __shared__ __align__(16) unsigned long long swd[C1 * 26];  // stride 26 -> 16B pairs
    __shared__ float sm[C1];
    int img = blockIdx.x, t = threadIdx.x;
    for (int i = t; i < 1024; i += 224) sx[i] = x[img * 1024 + i];
    for (int i = t; i < C1 * 25; i += 224) {
        int c = i / 25, p = i % 25;
        float v = w1[i];
        swd[c * 26 + p] = pack2(v, v);
    }
    if (t < C1) sm[t] = g_mean[t];
    __syncthreads();
    if (t < P1PIX) {
        int py = t / 14, px = t % 14;
        // packed pairs: P[r][k] = (win[r][k], win[r][k+1])  — positions dx=0 / dx=1
        unsigned long long P[6][5];
#pragma unroll
        for (int r = 0; r < 6; r++) {
            float c0 = sx[(py * 2 + r) * 32 + px * 2 + 0];
            float c1 = sx[(py * 2 + r) * 32 + px * 2 + 1];
            float c2 = sx[(py * 2 + r) * 32 + px * 2 + 2];
            float c3 = sx[(py * 2 + r) * 32 + px * 2 + 3];
            float c4 = sx[(py * 2 + r) * 32 + px * 2 + 4];
            float c5 = sx[(py * 2 + r) * 32 + px * 2 + 5];
            P[r][0] = pack2(c0, c1);
            P[r][1] = pack2(c1, c2);
            P[r][2] = pack2(c2, c3);
            P[r][3] = pack2(c3, c4);
            P[r][4] = pack2(c4, c5);
        }
        unsigned int bits = 0;
#pragma unroll 2
        for (int c = 0; c < C1; c++) {
            const unsigned long long* wc = &swd[c * 26];
            unsigned long long a0 = 0ull, a1 = 0ull;   // dy=0 / dy=1, dx in halves
#pragma unroll
            for (int p = 0; p < 24; p += 2) {
                ulonglong2 w = *reinterpret_cast<const ulonglong2*>(&wc[p]);
                a0 = fma2(P[(p) / 5][(p) % 5], w.x, a0);
                a1 = fma2(P[(p) / 5 + 1][(p) % 5], w.x, a1);
                a0 = fma2(P[(p + 1) / 5][(p + 1) % 5], w.y, a0);
                a1 = fma2(P[(p + 1) / 5 + 1][(p + 1) % 5], w.y, a1);
            }
            {
                unsigned long long w24 = wc[24];
                a0 = fma2(P[4][4], w24, a0);
                a1 = fma2(P[5][4], w24, a1);
            }
            float f00, f01, f10, f11;
            unpack2(a0, f00, f01);
            unpack2(a1, f10, f11);
            float m = fmaxf(fmaxf(f00, f01), fmaxf(f10, f11));
            if (m > sm[c]) bits |= (1u << c);
        }
        g_b1p[img * P1PIX + t] = bits;
    }
}

// ================= k4: XNOR conv2 + pool + sign (window cached over 5 oc) =================
__global__ void __launch_bounds__(256) k4_conv2() {
    __shared__ unsigned int sb[P1PIX];
    __shared__ unsigned int sw2[C2 * 25];
    __shared__ int spc[P1PIX];
    __shared__ int sS[100];
    __shared__ signed char s2b[1280];
    int img = blockIdx.x, t = threadIdx.x;
    for (int i = t; i < P1PIX; i += 256) sb[i] = g_b1p[img * P1PIX + i];
    for (int i = t; i < C2 * 25; i += 256) sw2[i] = g_w2p[i];
    __syncthreads();
    if (t < P1PIX) spc[t] = __popc(sb[t]);
    __syncthreads();
    if (t < 100) {
        int py = t / 10, px = t % 10;
        int s = 0;
#pragma unroll
        for (int ky = 0; ky < 5; ky++)
#pragma unroll
            for (int kx = 0; kx < 5; kx++)
                s += spc[(py + ky) * 14 + px + kx];
        sS[t] = s;
    }
    __syncthreads();
    if (t < 250) {
        int pp = t / 10, ocg = t % 10;       // pixel pp cached across 5 ocs
        int py = pp / 5, px = pp % 5;
        unsigned int win[6][6];
#pragma unroll
        for (int r = 0; r < 6; r++)
#pragma unroll
            for (int cc = 0; cc < 6; cc++)
                win[r][cc] = sb[(py * 2 + r) * 14 + px * 2 + cc];
        int b00 = sS[(2 * py) * 10 + 2 * px];
        int b01 = sS[(2 * py) * 10 + 2 * px + 1];
        int b10 = sS[(2 * py + 1) * 10 + 2 * px];
        int b11 = sS[(2 * py + 1) * 10 + 2 * px + 1];
#pragma unroll 1
        for (int j = 0; j < 5; j++) {
            int oc = ocg * 5 + j;
            const unsigned int* wr = &sw2[oc * 25];
            int A0 = 0, A1 = 0, A2 = 0, A3 = 0;
#pragma unroll
            for (int ky = 0; ky < 5; ky++)
#pragma unroll
                for (int kx = 0; kx < 5; kx++) {
                    unsigned wp = wr[ky * 5 + kx];
                    A0 += __popc(win[ky][kx] & wp);
                    A1 += __popc(win[ky][kx + 1] & wp);
                    A2 += __popc(win[ky + 1][kx] & wp);
                    A3 += __popc(win[ky + 1][kx + 1] & wp);
                }
            int a0 = 2 * A0 - b00;
            int a1 = 2 * A1 - b01;
            int a2 = 2 * A2 - b10;
            int a3 = 2 * A3 - b11;
            int best = max(max(a0, a1), max(a2, a3));
            s2b[oc * 25 + pp] = (signed char)((best > 0) - (best < 0));
        }
    }
    // zero padding slots
    for (int i = 1250 + t; i < 1280; i += 256) s2b[i] = 0;
    __syncthreads();
    int lane = t & 31;
#pragma unroll
    for (int it = 0; it < 5; it++) {
        int idx = it * 256 + t;
        int v = s2b[idx];
        unsigned bp = __ballot_sync(0xffffffffu, v > 0);
        unsigned bn = __ballot_sync(0xffffffffu, v < 0);
        if (lane == 0) g_s2p[img * NWRD + (idx >> 5)] = make_uint2(bp, bn);
    }
}

// ================= k5: popcount ternary linear + alpha + clip + fused fc =================
__global__ void __launch_bounds__(256) k5_linear(const float* __restrict__ fcw,
                                                 const float* __restrict__ fcb,
                                                 float* __restrict__ out) {
    __shared__ uint2 s2[IMGB * NWRD];     // (sp, sn) words
    __shared__ int   sD[IMGB];            // PSP - PSN per image
    __shared__ float sa[IMGB * LIN_OUT];  // clipped activations, 32 KB
    int blk = blockIdx.x, t = threadIdx.x;
    int n0 = blk * IMGB;
    for (int i = t; i < IMGB * NWRD; i += 256) s2[i] = g_s2p[n0 * NWRD + i];
    __syncthreads();
    if (t < IMGB) {
        int d = 0;
#pragma unroll
        for (int w = 0; w < NWRD; w++) {
            uint2 s = s2[t * NWRD + w];
            d += __popc(s.x) - __popc(s.y);
        }
        sD[t] = d;
    }
    __syncthreads();
    for (int oc = t; oc < LIN_OUT; oc += 256) {
        float al = g_alphal[oc];
        const unsigned int* wr = g_wpl + oc * NWRD;
        int acc[IMGB];
#pragma unroll
        for (int n = 0; n < IMGB; n++) acc[n] = 0;
#pragma unroll 4
        for (int w = 0; w < NWRD; w++) {
            unsigned wv = wr[w];
#pragma unroll
            for (int n = 0; n < IMGB; n++) {
                uint2 s = s2[n * NWRD + w];
                acc[n] += __popc(s.x & wv) - __popc(s.y & wv);
            }
        }
#pragma unroll
        for (int n = 0; n < IMGB; n++) {
            float v = (float)(2 * acc[n] - sD[n]) * al;
            v = fminf(1.f, fmaxf(-1.f, v));
            sa[n * LIN_OUT + oc] = v;
        }
    }
    __syncthreads();
    // fused fc: 16 images x 10 classes
    for (int i = t; i < IMGB * NCLS; i += 256) {
        int n = i / NCLS, cls = i % NCLS;
        const float* a = sa + n * LIN_OUT;
        const float* w = fcw + cls * LIN_OUT;
        float acc = 0.f;
#pragma unroll 4
        for (int k = 0; k < LIN_OUT; k++) acc += a[k] * w[k];
        out[(n0 + n) * NCLS + cls] = acc + fcb[cls];
    }
}

// ================= launch =================
extern "C" void kernel_launch(void* const* d_in, const int* in_sizes, int n_in,
                              void* d_out, int out_size) {
    const float* x   = (const float*)d_in[0];
    const float* w1  = (const float*)d_in[1];
    const float* w2  = (const float*)d_in[2];
    const float* wl  = (const float*)d_in[3];
    const float* fcw = (const float*)d_in[4];
    const float* fcb = (const float*)d_in[5];
    float* out = (float*)d_out;

    kw_pack  <<<256, 256>>>(w2, wl);
    k1_stats <<<NIMG, 256>>>(x, w1);
    k2_mean  <<<C1, 256>>>();
    k3_conv1 <<<NIMG, 224>>>(x, w1);
    k4_conv2 <<<NIMG, 256>>>();
    k5_linear<<<NIMG / IMGB, 256>>>(fcw, fcb, out);
}

// round 5
// speedup vs baseline: 1.9413x; 1.1104x over previous
#include <cuda_runtime.h>
#include <cuda_bf16.h>
#include <cstdint>

// ---------------- problem constants ----------------
#define NIMG   8192
#define C1     20
#define C2     50
#define P1PIX  196          // 14*14 pooled pixels after stage 1
#define LIN_IN 1250
#define NWRD   40           // ceil(1250/32)
#define LIN_OUT 500
#define NCLS   10
#define IMGB   16           // images per k5 block

// ---------------- device scratch ----------------
__device__ float        g_part[NIMG * C1];
__device__ float        g_mean[C1];
__device__ unsigned int g_b1p[NIMG * P1PIX];        // stage-1 bits, 20/pixel
__device__ unsigned int g_w2p[C2 * 25];             // conv2 positive-sign masks
__device__ unsigned int g_wpl[LIN_OUT * NWRD];      // linear positive-sign bitmask
__device__ float        g_alphal[LIN_OUT];
__device__ uint2        g_s2p[NIMG * NWRD];         // stage-2 (sp, sn) bit words
__device__ unsigned long long g_swd_stage[C1 * 26]; // duplicated conv1 weights (staging)

// ---------------- constant-memory conv1 params ----------------
__constant__ unsigned long long c_swd[C1 * 26];     // (w,w) pairs, stride 26
__constant__ float c_mean[C1];

// ---------------- f32x2 helpers ----------------
__device__ __forceinline__ unsigned long long pack2(float lo, float hi) {
    unsigned long long r;
    asm("mov.b64 %0, {%1, %2};" : "=l"(r) : "f"(lo), "f"(hi));
    return r;
}
__device__ __forceinline__ void unpack2(unsigned long long v, float& lo, float& hi) {
    asm("mov.b64 {%0, %1}, %2;" : "=f"(lo), "=f"(hi) : "l"(v));
}
__device__ __forceinline__ unsigned long long fma2(unsigned long long a,
                                                   unsigned long long b,
                                                   unsigned long long c) {
    unsigned long long d;
    asm("fma.rn.f32x2 %0, %1, %2, %3;" : "=l"(d) : "l"(a), "l"(b), "l"(c));
    return d;
}

// ================= kw: weight preprocessing (all-in-one) =================
__global__ void kw_pack(const float* __restrict__ w1, const float* __restrict__ w2,
                        const float* __restrict__ wl) {
    int gid = blockIdx.x * blockDim.x + threadIdx.x;
    int stride = gridDim.x * blockDim.x;
    // conv1 duplicated-weight staging
    for (int i = gid; i < C1 * 25; i += stride) {
        int c = i / 25, p = i % 25;
        float v = w1[i];
        g_swd_stage[c * 26 + p] = pack2(v, v);
    }
    // conv2 positive masks (weights are never exactly 0)
    for (int i = gid; i < C2 * 25; i += stride) {
        int oc = i / 25, p = i % 25;
        unsigned wp = 0;
        for (int ic = 0; ic < C1; ic++)
            if (w2[(oc * C1 + ic) * 25 + p] > 0.f) wp |= (1u << ic);
        g_w2p[i] = wp;
    }
    // linear sign bitmask
    for (int i = gid; i < LIN_OUT * NWRD; i += stride) {
        int oc = i / NWRD, w = i % NWRD;
        unsigned bits = 0;
        for (int j = 0; j < 32; j++) {
            int k = w * 32 + j;
            if (k < LIN_IN && wl[oc * LIN_IN + k] > 0.f) bits |= (1u << j);
        }
        g_wpl[i] = bits;
    }
    // alpha: one warp per output row
    for (int i = gid; i < LIN_OUT * 32; i += stride) {
        int oc = i >> 5, lane = i & 31;
        float s = 0.f;
        for (int k = lane; k < LIN_IN; k += 32) s += fabsf(wl[oc * LIN_IN + k]);
#pragma unroll
        for (int off = 16; off > 0; off >>= 1)
            s += __shfl_down_sync(0xffffffffu, s, off);
        if (lane == 0) g_alphal[oc] = s * (1.f / (float)LIN_IN);
    }
}

// ================= k1: per-image conv1 channel sums via window sums =================
__global__ void k1_stats(const float* __restrict__ x, const float* __restrict__ w1) {
    int img = blockIdx.x, t = threadIdx.x;         // 256 threads
    __shared__ float sR[32 * 5];
    __shared__ float sS[25];
    __shared__ float sw[C1 * 25];
    for (int i = t; i < C1 * 25; i += 256) sw[i] = w1[i];
    int warp = t >> 5, lane = t & 31;
    for (int r = warp; r < 32; r += 8) {
        float v = x[img * 1024 + r * 32 + lane];
        float p = v;
#pragma unroll
        for (int off = 1; off < 32; off <<= 1) {
            float o = __shfl_up_sync(0xffffffffu, p, off);
            if (lane >= off) p += o;
        }
        float lo = __shfl_up_sync(0xffffffffu, p, 1);
        if (lane == 0) lo = 0.f;
        float hi = __shfl_sync(0xffffffffu, p, (lane + 27) & 31);
        if (lane < 5) sR[r * 5 + lane] = hi - lo;
    }
    __syncthreads();
    if (t < 25) {
        int ky = t / 5, kx = t % 5;
        float s = 0.f;
        for (int r = ky; r < ky + 28; r++) s += sR[r * 5 + kx];
        sS[t] = s;
    }
    __syncthreads();
    if (t < C1) {
        float a = 0.f;
#pragma unroll
        for (int p = 0; p < 25; p++) a += sw[t * 25 + p] * sS[p];
        g_part[img * C1 + t] = a;
    }
}

// ================= k2: deterministic channel-mean reduction =================
__global__ void k2_mean() {
    int c = blockIdx.x, t = threadIdx.x;
    __shared__ float red[256];
    float s = 0.f;
    for (int i = t; i < NIMG; i += 256) s += g_part[i * C1 + c];
    red[t] = s;
    __syncthreads();
    for (int o = 128; o > 0; o >>= 1) {
        if (t < o) red[t] += red[t + o];
        __syncthreads();
    }
    if (t == 0) g_mean[c] = red[0] * (1.0f / (8192.f * 784.f));
}

// ================= k3: conv1 + threshold + pool + sign, FFMA2, const weights =================
#define K3_T 416
__global__ void __launch_bounds__(K3_T) k3_conv1(const float* __restrict__ x) {
    __shared__ float sx[2048];               // 2 images
    int t = threadIdx.x;
    int base = blockIdx.x * 2048;
    for (int i = t; i < 2048; i += K3_T) sx[i] = x[base + i];
    __syncthreads();
    if (t < 392) {
        int il = t / 196, pp = t % 196;
        int py = pp / 14, px = pp % 14;
        const float* sxi = sx + il * 1024;
        // packed pairs: P[r][k] = (win[r][k], win[r][k+1])  — positions dx=0 / dx=1
        unsigned long long P[6][5];
#pragma unroll
        for (int r = 0; r < 6; r++) {
            float c0 = sxi[(py * 2 + r) * 32 + px * 2 + 0];
            float c1 = sxi[(py * 2 + r) * 32 + px * 2 + 1];
            float c2 = sxi[(py * 2 + r) * 32 + px * 2 + 2];
            float c3 = sxi[(py * 2 + r) * 32 + px * 2 + 3];
            float c4 = sxi[(py * 2 + r) * 32 + px * 2 + 4];
            float c5 = sxi[(py * 2 + r) * 32 + px * 2 + 5];
            P[r][0] = pack2(c0, c1);
            P[r][1] = pack2(c1, c2);
            P[r][2] = pack2(c2, c3);
            P[r][3] = pack2(c3, c4);
            P[r][4] = pack2(c4, c5);
        }
        unsigned int bits = 0;
#pragma unroll 2
        for (int c = 0; c < C1; c++) {
            const unsigned long long* wc = &c_swd[c * 26];
            unsigned long long a0 = 0ull, a1 = 0ull;   // dy=0 / dy=1, dx in halves
#pragma unroll
            for (int p = 0; p < 25; p++) {
                unsigned long long w = wc[p];
                a0 = fma2(P[p / 5][p % 5], w, a0);
                a1 = fma2(P[p / 5 + 1][p % 5], w, a1);
            }
            float f00, f01, f10, f11;
            unpack2(a0, f00, f01);
            unpack2(a1, f10, f11);
            float m = fmaxf(fmaxf(f00, f01), fmaxf(f10, f11));
            if (m > c_mean[c]) bits |= (1u << c);
        }
        g_b1p[(blockIdx.x * 2 + il) * P1PIX + pp] = bits;
    }
}

// ================= k4: XNOR conv2 + pool + sign (window cached over 5 oc) =================
__global__ void __launch_bounds__(256) k4_conv2() {
    __shared__ __align__(8) unsigned int sb[P1PIX];
    __shared__ unsigned int sw2[C2 * 25];
    __shared__ int spc[P1PIX];
    __shared__ int sS[100];
    __shared__ signed char s2b[1280];
    int img = blockIdx.x, t = threadIdx.x;
    for (int i = t; i < P1PIX; i += 256) {
        unsigned v = g_b1p[img * P1PIX + i];
        sb[i] = v;
        spc[i] = __popc(v);
    }
    for (int i = t; i < C2 * 25; i += 256) sw2[i] = g_w2p[i];
    __syncthreads();
    if (t < 100) {
        int py = t / 10, px = t % 10;
        int s = 0;
#pragma unroll
        for (int ky = 0; ky < 5; ky++)
#pragma unroll
            for (int kx = 0; kx < 5; kx++)
                s += spc[(py + ky) * 14 + px + kx];
        sS[t] = s;
    }
    __syncthreads();
    if (t < 250) {
        int pp = t / 10, ocg = t % 10;       // pixel pp cached across 5 ocs
        int py = pp / 5, px = pp % 5;
        unsigned int win[6][6];
#pragma unroll
        for (int r = 0; r < 6; r++) {
            const uint2* row = reinterpret_cast<const uint2*>(sb + (py * 2 + r) * 14 + px * 2);
            uint2 v0 = row[0], v1 = row[1], v2 = row[2];
            win[r][0] = v0.x; win[r][1] = v0.y;
            win[r][2] = v1.x; win[r][3] = v1.y;
            win[r][4] = v2.x; win[r][5] = v2.y;
        }
        int b00 = sS[(2 * py) * 10 + 2 * px];
        int b01 = sS[(2 * py) * 10 + 2 * px + 1];
        int b10 = sS[(2 * py + 1) * 10 + 2 * px];
        int b11 = sS[(2 * py + 1) * 10 + 2 * px + 1];
#pragma unroll 1
        for (int j = 0; j < 5; j++) {
            int oc = ocg * 5 + j;
            const unsigned int* wr = &sw2[oc * 25];
            int A0 = 0, A1 = 0, A2 = 0, A3 = 0;
#pragma unroll
            for (int ky = 0; ky < 5; ky++)
#pragma unroll
                for (int kx = 0; kx < 5; kx++) {
                    unsigned wp = wr[ky * 5 + kx];
                    A0 += __popc(win[ky][kx] & wp);
                    A1 += __popc(win[ky][kx + 1] & wp);
                    A2 += __popc(win[ky + 1][kx] & wp);
                    A3 += __popc(win[ky + 1][kx + 1] & wp);
                }
            int a0 = 2 * A0 - b00;
            int a1 = 2 * A1 - b01;
            int a2 = 2 * A2 - b10;
            int a3 = 2 * A3 - b11;
            int best = max(max(a0, a1), max(a2, a3));
            s2b[oc * 25 + pp] = (signed char)((best > 0) - (best < 0));
        }
    }
    for (int i = 1250 + t; i < 1280; i += 256) s2b[i] = 0;
    __syncthreads();
    int lane = t & 31;
#pragma unroll
    for (int it = 0; it < 5; it++) {
        int idx = it * 256 + t;
        int v = s2b[idx];
        unsigned bp = __ballot_sync(0xffffffffu, v > 0);
        unsigned bn = __ballot_sync(0xffffffffu, v < 0);
        if (lane == 0) g_s2p[img * NWRD + (idx >> 5)] = make_uint2(bp, bn);
    }
}

// ================= k5: popcount ternary linear + alpha + clip + fused fc =================
__global__ void __launch_bounds__(256) k5_linear(const float* __restrict__ fcw,
                                                 const float* __restrict__ fcb,
                                                 float* __restrict__ out) {
    __shared__ uint2 s2[IMGB * NWRD];     // (sp, sn) words
    __shared__ int   sD[IMGB];            // PSP - PSN per image
    __shared__ float sa[IMGB * LIN_OUT];  // clipped activations, 32 KB
    int blk = blockIdx.x, t = threadIdx.x;
    int n0 = blk * IMGB;
    for (int i = t; i < IMGB * NWRD; i += 256) s2[i] = g_s2p[n0 * NWRD + i];
    __syncthreads();
    if (t < IMGB) {
        int d = 0;
#pragma unroll
        for (int w = 0; w < NWRD; w++) {
            uint2 s = s2[t * NWRD + w];
            d += __popc(s.x) - __popc(s.y);
        }
        sD[t] = d;
    }
    __syncthreads();
    for (int oc = t; oc < LIN_OUT; oc += 256) {
        float al = g_alphal[oc];
        const unsigned int* wr = g_wpl + oc * NWRD;
        int acc[IMGB];
#pragma unroll
        for (int n = 0; n < IMGB; n++) acc[n] = 0;
#pragma unroll 4
        for (int w = 0; w < NWRD; w++) {
            unsigned wv = wr[w];
#pragma unroll
            for (int n = 0; n < IMGB; n++) {
                uint2 s = s2[n * NWRD + w];
                acc[n] += __popc(s.x & wv) - __popc(s.y & wv);
            }
        }
#pragma unroll
        for (int n = 0; n < IMGB; n++) {
            float v = (float)(2 * acc[n] - sD[n]) * al;
            v = fminf(1.f, fmaxf(-1.f, v));
            sa[n * LIN_OUT + oc] = v;
        }
    }
    __syncthreads();
    // fused fc: 16 images x 10 classes
    for (int i = t; i < IMGB * NCLS; i += 256) {
        int n = i / NCLS, cls = i % NCLS;
        const float* a = sa + n * LIN_OUT;
        const float* w = fcw + cls * LIN_OUT;
        float acc = 0.f;
#pragma unroll 4
        for (int k = 0; k < LIN_OUT; k++) acc += a[k] * w[k];
        out[(n0 + n) * NCLS + cls] = acc + fcb[cls];
    }
}

// ================= launch =================
extern "C" void kernel_launch(void* const* d_in, const int* in_sizes, int n_in,
                              void* d_out, int out_size) {
    const float* x   = (const float*)d_in[0];
    const float* w1  = (const float*)d_in[1];
    const float* w2  = (const float*)d_in[2];
    const float* wl  = (const float*)d_in[3];
    const float* fcw = (const float*)d_in[4];
    const float* fcb = (const float*)d_in[5];
    float* out = (float*)d_out;

    kw_pack  <<<256, 256>>>(w1, w2, wl);
    k1_stats <<<NIMG, 256>>>(x, w1);
    k2_mean  <<<C1, 256>>>();

    // stage -> constant memory (graph-capturable D2D memcpy nodes)
    void* p_swd = nullptr;
    void* p_mean = nullptr;
    cudaGetSymbolAddress(&p_swd, g_swd_stage);
    cudaGetSymbolAddress(&p_mean, g_mean);
    cudaMemcpyToSymbolAsync(c_swd, p_swd, C1 * 26 * sizeof(unsigned long long), 0,
                            cudaMemcpyDeviceToDevice, 0);
    cudaMemcpyToSymbolAsync(c_mean, p_mean, C1 * sizeof(float), 0,
                            cudaMemcpyDeviceToDevice, 0);

    k3_conv1 <<<NIMG / 2, K3_T>>>(x);
    k4_conv2 <<<NIMG, 256>>>();
    k5_linear<<<NIMG / IMGB, 256>>>(fcw, fcb, out);
}

// round 7
// speedup vs baseline: 1.9748x; 1.0172x over previous
#include <cuda_runtime.h>
#include <cuda_bf16.h>
#include <cstdint>

// ---------------- problem constants ----------------
#define NIMG   8192
#define C1     20
#define C2     50
#define P1PIX  196          // 14*14 pooled pixels after stage 1
#define LIN_IN 1250
#define NWRD   40           // ceil(1250/32)
#define LIN_OUT 500
#define NCLS   10
#define IMGB   16           // images per k5 block

// ---------------- device scratch ----------------
__device__ float        g_part[NIMG * C1];
__device__ float        g_mean[C1];
__device__ unsigned int g_b1p[NIMG * P1PIX];        // stage-1 bits, 20/pixel
__device__ unsigned int g_w2p[C2 * 25];             // conv2 positive-sign masks
__device__ unsigned int g_wpl[LIN_OUT * NWRD];      // linear positive-sign bitmask
__device__ float        g_alphal[LIN_OUT];
__device__ uint2        g_s2p[NIMG * NWRD];         // stage-2 (sp, sn) bit words
__device__ unsigned long long g_swd_stage[C1 * 26]; // duplicated conv1 weights (staging)

// ---------------- constant-memory conv1 params ----------------
__constant__ unsigned long long c_swd[C1 * 26];     // (w,w) pairs, stride 26 (208B, 16-aligned)
__constant__ float c_mean[C1];

// ---------------- f32x2 helpers ----------------
__device__ __forceinline__ unsigned long long pack2(float lo, float hi) {
    unsigned long long r;
    asm("mov.b64 %0, {%1, %2};" : "=l"(r) : "f"(lo), "f"(hi));
    return r;
}
__device__ __forceinline__ void unpack2(unsigned long long v, float& lo, float& hi) {
    asm("mov.b64 {%0, %1}, %2;" : "=f"(lo), "=f"(hi) : "l"(v));
}
__device__ __forceinline__ unsigned long long fma2(unsigned long long a,
                                                   unsigned long long b,
                                                   unsigned long long c) {
    unsigned long long d;
    asm("fma.rn.f32x2 %0, %1, %2, %3;" : "=l"(d) : "l"(a), "l"(b), "l"(c));
    return d;
}

// ================= kw: weight preprocessing (all-in-one) =================
__global__ void kw_pack(const float* __restrict__ w1, const float* __restrict__ w2,
                        const float* __restrict__ wl) {
    int gid = blockIdx.x * blockDim.x + threadIdx.x;
    int stride = gridDim.x * blockDim.x;
    // conv1 duplicated-weight staging
    for (int i = gid; i < C1 * 25; i += stride) {
        int c = i / 25, p = i % 25;
        float v = w1[i];
        g_swd_stage[c * 26 + p] = pack2(v, v);
    }
    // conv2 positive masks (weights are never exactly 0)
    for (int i = gid; i < C2 * 25; i += stride) {
        int oc = i / 25, p = i % 25;
        unsigned wp = 0;
        for (int ic = 0; ic < C1; ic++)
            if (w2[(oc * C1 + ic) * 25 + p] > 0.f) wp |= (1u << ic);
        g_w2p[i] = wp;
    }
    // linear sign bitmask
    for (int i = gid; i < LIN_OUT * NWRD; i += stride) {
        int oc = i / NWRD, w = i % NWRD;
        unsigned bits = 0;
        for (int j = 0; j < 32; j++) {
            int k = w * 32 + j;
            if (k < LIN_IN && wl[oc * LIN_IN + k] > 0.f) bits |= (1u << j);
        }
        g_wpl[i] = bits;
    }
    // alpha: one warp per output row
    for (int i = gid; i < LIN_OUT * 32; i += stride) {
        int oc = i >> 5, lane = i & 31;
        float s = 0.f;
        for (int k = lane; k < LIN_IN; k += 32) s += fabsf(wl[oc * LIN_IN + k]);
#pragma unroll
        for (int off = 16; off > 0; off >>= 1)
            s += __shfl_down_sync(0xffffffffu, s, off);
        if (lane == 0) g_alphal[oc] = s * (1.f / (float)LIN_IN);
    }
}

// ================= k1: per-image conv1 channel sums via window sums =================
__global__ void k1_stats(const float* __restrict__ x, const float* __restrict__ w1) {
    int img = blockIdx.x, t = threadIdx.x;         // 256 threads
    __shared__ float sR[32 * 5];
    __shared__ float sS[25];
    __shared__ float sw[C1 * 25];
    for (int i = t; i < C1 * 25; i += 256) sw[i] = w1[i];
    int warp = t >> 5, lane = t & 31;
    for (int r = warp; r < 32; r += 8) {
        float v = x[img * 1024 + r * 32 + lane];
        float p = v;
#pragma unroll
        for (int off = 1; off < 32; off <<= 1) {
            float o = __shfl_up_sync(0xffffffffu, p, off);
            if (lane >= off) p += o;
        }
        float lo = __shfl_up_sync(0xffffffffu, p, 1);
        if (lane == 0) lo = 0.f;
        float hi = __shfl_sync(0xffffffffu, p, (lane + 27) & 31);
        if (lane < 5) sR[r * 5 + lane] = hi - lo;
    }
    __syncthreads();
    if (t < 25) {
        int ky = t / 5, kx = t % 5;
        float s = 0.f;
        for (int r = ky; r < ky + 28; r++) s += sR[r * 5 + kx];
        sS[t] = s;
    }
    __syncthreads();
    if (t < C1) {
        float a = 0.f;
#pragma unroll
        for (int p = 0; p < 25; p++) a += sw[t * 25 + p] * sS[p];
        g_part[img * C1 + t] = a;
    }
}

// ================= k2: deterministic channel-mean reduction =================
__global__ void k2_mean() {
    int c = blockIdx.x, t = threadIdx.x;
    __shared__ float red[256];
    float s = 0.f;
    for (int i = t; i < NIMG; i += 256) s += g_part[i * C1 + c];
    red[t] = s;
    __syncthreads();
    for (int o = 128; o > 0; o >>= 1) {
        if (t < o) red[t] += red[t + o];
        __syncthreads();
    }
    if (t == 0) g_mean[c] = red[0] * (1.0f / (8192.f * 784.f));
}

// ================= k3: conv1 + threshold + pool + sign, FFMA2, const.128 weights =================
#define K3_T 416
__global__ void __launch_bounds__(K3_T) k3_conv1(const float* __restrict__ x) {
    __shared__ float sx[2048];               // 2 images
    int t = threadIdx.x;
    int base = blockIdx.x * 2048;
    for (int i = t; i < 2048; i += K3_T) sx[i] = x[base + i];
    __syncthreads();
    if (t < 392) {
        int il = t / 196, pp = t % 196;
        int py = pp / 14, px = pp % 14;
        const float* sxi = sx + il * 1024;
        // packed pairs: P[r][k] = (win[r][k], win[r][k+1])  — positions dx=0 / dx=1
        unsigned long long P[6][5];
#pragma unroll
        for (int r = 0; r < 6; r++) {
            float c0 = sxi[(py * 2 + r) * 32 + px * 2 + 0];
            float c1 = sxi[(py * 2 + r) * 32 + px * 2 + 1];
            float c2 = sxi[(py * 2 + r) * 32 + px * 2 + 2];
            float c3 = sxi[(py * 2 + r) * 32 + px * 2 + 3];
            float c4 = sxi[(py * 2 + r) * 32 + px * 2 + 4];
            float c5 = sxi[(py * 2 + r) * 32 + px * 2 + 5];
            P[r][0] = pack2(c0, c1);
            P[r][1] = pack2(c1, c2);
            P[r][2] = pack2(c2, c3);
            P[r][3] = pack2(c3, c4);
            P[r][4] = pack2(c4, c5);
        }
        unsigned int bits = 0;
#pragma unroll
        for (int c = 0; c < C1; c++) {
            // 12 x 128-bit constant loads + 1 x 64-bit (c*26*8 = 208B, 16B-aligned)
            const ulonglong2* wc2 = reinterpret_cast<const ulonglong2*>(&c_swd[c * 26]);
            unsigned long long a0 = 0ull, a1 = 0ull;   // dy=0 / dy=1, dx in halves
#pragma unroll
            for (int q = 0; q < 12; q++) {
                ulonglong2 w = wc2[q];
                int p0 = 2 * q, p1 = 2 * q + 1;
                a0 = fma2(P[p0 / 5][p0 % 5], w.x, a0);
                a1 = fma2(P[p0 / 5 + 1][p0 % 5], w.x, a1);
                a0 = fma2(P[p1 / 5][p1 % 5], w.y, a0);
                a1 = fma2(P[p1 / 5 + 1][p1 % 5], w.y, a1);
            }
            {
                unsigned long long w24 = c_swd[c * 26 + 24];
                a0 = fma2(P[4][4], w24, a0);
                a1 = fma2(P[5][4], w24, a1);
            }
            float f00, f01, f10, f11;
            unpack2(a0, f00, f01);
            unpack2(a1, f10, f11);
            float m = fmaxf(fmaxf(f00, f01), fmaxf(f10, f11));
            if (m > c_mean[c]) bits |= (1u << c);
        }
        g_b1p[(blockIdx.x * 2 + il) * P1PIX + pp] = bits;
    }
}

// ================= k4: XNOR conv2 + pool + sign (window cached over 5 oc) =================
__global__ void __launch_bounds__(256) k4_conv2() {
    __shared__ __align__(8) unsigned int sb[P1PIX];
    __shared__ unsigned int sw2[C2 * 25];
    __shared__ int spc[P1PIX];
    __shared__ int sS[100];
    __shared__ signed char s2b[1280];
    int img = blockIdx.x, t = threadIdx.x;
    for (int i = t; i < P1PIX; i += 256) {
        unsigned v = g_b1p[img * P1PIX + i];
        sb[i] = v;
        spc[i] = __popc(v);
    }
    for (int i = t; i < C2 * 25; i += 256) sw2[i] = g_w2p[i];
    __syncthreads();
    if (t < 100) {
        int py = t / 10, px = t % 10;
        int s = 0;
#pragma unroll
        for (int ky = 0; ky < 5; ky++)
#pragma unroll
            for (int kx = 0; kx < 5; kx++)
                s += spc[(py + ky) * 14 + px + kx];
        sS[t] = s;
    }
    __syncthreads();
    if (t < 250) {
        int pp = t / 10, ocg = t % 10;       // pixel pp cached across 5 ocs
        int py = pp / 5, px = pp % 5;
        unsigned int win[6][6];
#pragma unroll
        for (int r = 0; r < 6; r++) {
            const uint2* row = reinterpret_cast<const uint2*>(sb + (py * 2 + r) * 14 + px * 2);
            uint2 v0 = row[0], v1 = row[1], v2 = row[2];
            win[r][0] = v0.x; win[r][1] = v0.y;
            win[r][2] = v1.x; win[r][3] = v1.y;
            win[r][4] = v2.x; win[r][5] = v2.y;
        }
        int b00 = sS[(2 * py) * 10 + 2 * px];
        int b01 = sS[(2 * py) * 10 + 2 * px + 1];
        int b10 = sS[(2 * py + 1) * 10 + 2 * px];
        int b11 = sS[(2 * py + 1) * 10 + 2 * px + 1];
#pragma unroll 1
        for (int j = 0; j < 5; j++) {
            int oc = ocg * 5 + j;
            const unsigned int* wr = &sw2[oc * 25];
            int A0 = 0, A1 = 0, A2 = 0, A3 = 0;
#pragma unroll
            for (int ky = 0; ky < 5; ky++) {
                unsigned w0 = wr[ky * 5 + 0], w1 = wr[ky * 5 + 1], w2 = wr[ky * 5 + 2];
                unsigned w3 = wr[ky * 5 + 3], w4 = wr[ky * 5 + 4];
                // pairwise grouping -> IADD3-friendly trees
                A0 += (__popc(win[ky][0 + 0] & w0) + __popc(win[ky][1 + 0] & w1))
                    + (__popc(win[ky][2 + 0] & w2) + __popc(win[ky][3 + 0] & w3))
                    +  __popc(win[ky][4 + 0] & w4);
                A1 += (__popc(win[ky][0 + 1] & w0) + __popc(win[ky][1 + 1] & w1))
                    + (__popc(win[ky][2 + 1] & w2) + __popc(win[ky][3 + 1] & w3))
                    +  __popc(win[ky][4 + 1] & w4);
                A2 += (__popc(win[ky + 1][0 + 0] & w0) + __popc(win[ky + 1][1 + 0] & w1))
                    + (__popc(win[ky + 1][2 + 0] & w2) + __popc(win[ky + 1][3 + 0] & w3))
                    +  __popc(win[ky + 1][4 + 0] & w4);
                A3 += (__popc(win[ky + 1][0 + 1] & w0) + __popc(win[ky + 1][1 + 1] & w1))
                    + (__popc(win[ky + 1][2 + 1] & w2) + __popc(win[ky + 1][3 + 1] & w3))
                    +  __popc(win[ky + 1][4 + 1] & w4);
            }
            int a0 = 2 * A0 - b00;
            int a1 = 2 * A1 - b01;
            int a2 = 2 * A2 - b10;
            int a3 = 2 * A3 - b11;
            int best = max(max(a0, a1), max(a2, a3));
            s2b[oc * 25 + pp] = (signed char)((best > 0) - (best < 0));
        }
    }
    for (int i = 1250 + t; i < 1280; i += 256) s2b[i] = 0;
    __syncthreads();
    int lane = t & 31;
#pragma unroll
    for (int it = 0; it < 5; it++) {
        int idx = it * 256 + t;
        int v = s2b[idx];
        unsigned bp = __ballot_sync(0xffffffffu, v > 0);
        unsigned bn = __ballot_sync(0xffffffffu, v < 0);
        if (lane == 0) g_s2p[img * NWRD + (idx >> 5)] = make_uint2(bp, bn);
    }
}

// ================= k5: popcount ternary linear + alpha + clip + fused fc =================
__global__ void __launch_bounds__(256) k5_linear(const float* __restrict__ fcw,
                                                 const float* __restrict__ fcb,
                                                 float* __restrict__ out) {
    __shared__ __align__(16) uint4 s2[IMGB * (NWRD / 2)];  // {sp_w, sn_w, sp_w+1, sn_w+1}
    __shared__ int   sD[IMGB];            // PSP - PSN per image
    __shared__ float sa[IMGB * LIN_OUT];  // clipped activations, 32 KB
    int blk = blockIdx.x, t = threadIdx.x;
    int n0 = blk * IMGB;
    const uint4* src = reinterpret_cast<const uint4*>(g_s2p + (size_t)n0 * NWRD);
    for (int i = t; i < IMGB * (NWRD / 2); i += 256) s2[i] = src[i];
    __syncthreads();
    if (t < IMGB) {
        int d = 0;
#pragma unroll
        for (int w = 0; w < NWRD / 2; w++) {
            uint4 s = s2[t * (NWRD / 2) + w];
            d += (__popc(s.x) - __popc(s.y)) + (__popc(s.z) - __popc(s.w));
        }
        sD[t] = d;
    }
    __syncthreads();
    for (int oc = t; oc < LIN_OUT; oc += 256) {
        float al = g_alphal[oc];
        const uint2* wr = reinterpret_cast<const uint2*>(g_wpl + oc * NWRD);
        int acc[IMGB];
#pragma unroll
        for (int n = 0; n < IMGB; n++) acc[n] = 0;
#pragma unroll 2
        for (int w = 0; w < NWRD / 2; w++) {
            uint2 wv = wr[w];
#pragma unroll
            for (int n = 0; n < IMGB; n++) {
                uint4 s = s2[n * (NWRD / 2) + w];
                acc[n] += (__popc(s.x & wv.x) - __popc(s.y & wv.x))
                        + (__popc(s.z & wv.y) - __popc(s.w & wv.y));
            }
        }
#pragma unroll
        for (int n = 0; n < IMGB; n++) {
            float v = (float)(2 * acc[n] - sD[n]) * al;
            v = fminf(1.f, fmaxf(-1.f, v));
            sa[n * LIN_OUT + oc] = v;
        }
    }
    __syncthreads();
    // fused fc: 16 images x 10 classes
    for (int i = t; i < IMGB * NCLS; i += 256) {
        int n = i / NCLS, cls = i % NCLS;
        const float* a = sa + n * LIN_OUT;
        const float* w = fcw + cls * LIN_OUT;
        float acc = 0.f;
#pragma unroll 4
        for (int k = 0; k < LIN_OUT; k++) acc += a[k] * w[k];
        out[(n0 + n) * NCLS + cls] = acc + fcb[cls];
    }
}

// ================= launch =================
extern "C" void kernel_launch(void* const* d_in, const int* in_sizes, int n_in,
                              void* d_out, int out_size) {
    const float* x   = (const float*)d_in[0];
    const float* w1  = (const float*)d_in[1];
    const float* w2  = (const float*)d_in[2];
    const float* wl  = (const float*)d_in[3];
    const float* fcw = (const float*)d_in[4];
    const float* fcb = (const float*)d_in[5];
    float* out = (float*)d_out;

    kw_pack  <<<256, 256>>>(w1, w2, wl);
    k1_stats <<<NIMG, 256>>>(x, w1);
    k2_mean  <<<C1, 256>>>();

    // stage -> constant memory (graph-capturable D2D memcpy nodes)
    void* p_swd = nullptr;
    void* p_mean = nullptr;
    cudaGetSymbolAddress(&p_swd, g_swd_stage);
    cudaGetSymbolAddress(&p_mean, g_mean);
    cudaMemcpyToSymbolAsync(c_swd, p_swd, C1 * 26 * sizeof(unsigned long long), 0,
                            cudaMemcpyDeviceToDevice, 0);
    cudaMemcpyToSymbolAsync(c_mean, p_mean, C1 * sizeof(float), 0,
                            cudaMemcpyDeviceToDevice, 0);

    k3_conv1 <<<NIMG / 2, K3_T>>>(x);
    k4_conv2 <<<NIMG, 256>>>();
    k5_linear<<<NIMG / IMGB, 256>>>(fcw, fcb, out);
}